// round 15
// baseline (speedup 1.0000x reference)
#include <cuda_runtime.h>
#include <cuda_fp16.h>
#include <cstdint>

#define EPSV 1e-9f

// Fixed problem shape: B=16384, IN=K=2048, OUT=2048
#define B_DIM   16384
#define K_DIM   2048
#define O_DIM   2048

// ---------------------------------------------------------------------------
// Device scratch (no allocations allowed in kernel_launch)
// ---------------------------------------------------------------------------
__device__ uint16_t g_u[(size_t)B_DIM * O_DIM];   // relu(cos) scratch, unorm16 (64 MB)
__device__ float g_gmax;
__device__ __align__(16) __half g_xh[(size_t)B_DIM * K_DIM];  // normalized x, fp16
__device__ __align__(16) __half g_wh[(size_t)O_DIM * K_DIM];  // normalized w, fp16

// ---------------------------------------------------------------------------
// PTX helpers (family-safe: ldmatrix, mma.sync, cp.async)
// ---------------------------------------------------------------------------
__device__ __forceinline__ uint32_t smem_u32(const void* p) {
    uint32_t a;
    asm("{ .reg .u64 t; cvta.to.shared.u64 t, %1; cvt.u32.u64 %0, t; }"
        : "=r"(a) : "l"(p));
    return a;
}

#define CP16(saddr, gptr) \
    asm volatile("cp.async.cg.shared.global [%0], [%1], 16;" \
                 :: "r"(saddr), "l"(gptr) : "memory")
#define CP_COMMIT() asm volatile("cp.async.commit_group;" ::: "memory")
#define CP_WAIT1()  asm volatile("cp.async.wait_group 1;" ::: "memory")

#define LDSM_X4(r0, r1, r2, r3, addr) \
    asm volatile("ldmatrix.sync.aligned.m8n8.x4.shared.b16 {%0,%1,%2,%3}, [%4];" \
                 : "=r"(r0), "=r"(r1), "=r"(r2), "=r"(r3) : "r"(addr))

#define MMA_F16(d, a, b) \
    asm volatile("mma.sync.aligned.m16n8k16.row.col.f32.f16.f16.f32 " \
                 "{%0,%1,%2,%3}, {%4,%5,%6,%7}, {%8,%9}, {%0,%1,%2,%3};" \
                 : "+f"((d)[0]), "+f"((d)[1]), "+f"((d)[2]), "+f"((d)[3]) \
                 : "r"((a)[0]), "r"((a)[1]), "r"((a)[2]), "r"((a)[3]),   \
                   "r"((b)[0]), "r"((b)[1]))

// Streaming store (evict-first): for outputs never re-read.
#define STG_CS_V4(ptr, v) \
    asm volatile("st.global.cs.v4.f32 [%0], {%1,%2,%3,%4};" \
                 :: "l"(ptr), "f"((v).x), "f"((v).y), "f"((v).z), "f"((v).w) \
                 : "memory")

// ---------------------------------------------------------------------------
// Kernel 1: per-row L2 normalize -> fp16. Warp-per-row, reg-resident,
// shfl-only reduction, no smem/barriers. 8 rows per 256-thread block.
// Rows [0,B): x -> g_xh; [B,B+OUT): w -> g_wh. Block 0 resets g_gmax.
// ---------------------------------------------------------------------------
__global__ void __launch_bounds__(256)
prep_kernel(const float* __restrict__ x, const float* __restrict__ w,
            int B, int OUT, int IN)
{
    const int warp = threadIdx.x >> 5;
    const int lane = threadIdx.x & 31;
    const int r = blockIdx.x * 8 + warp;

    if (blockIdx.x == 0 && threadIdx.x == 0) g_gmax = 0.f;
    if (r >= B + OUT) return;

    const float* src;
    __half* dst;
    if (r < B) { src = x + (size_t)r * IN;       dst = g_xh + (size_t)r * IN; }
    else       { src = w + (size_t)(r - B) * IN; dst = g_wh + (size_t)(r - B) * IN; }

    const float4* p4 = reinterpret_cast<const float4*>(src);
    float4 v[16];
    #pragma unroll
    for (int j = 0; j < 16; ++j) v[j] = __ldg(&p4[lane + j * 32]);

    float s = 0.f;
    #pragma unroll
    for (int j = 0; j < 16; ++j)
        s += v[j].x * v[j].x + v[j].y * v[j].y + v[j].z * v[j].z + v[j].w * v[j].w;

    #pragma unroll
    for (int o = 16; o; o >>= 1) s += __shfl_xor_sync(0xffffffffu, s, o);
    const float sc = 1.f / (sqrtf(s) + EPSV);

    uint2* d2 = reinterpret_cast<uint2*>(dst);
    #pragma unroll
    for (int j = 0; j < 16; ++j) {
        __half2 lo = __floats2half2_rn(v[j].x * sc, v[j].y * sc);
        __half2 hi = __floats2half2_rn(v[j].z * sc, v[j].w * sc);
        uint2 u;
        u.x = *reinterpret_cast<uint32_t*>(&lo);
        u.y = *reinterpret_cast<uint32_t*>(&hi);
        d2[lane + j * 32] = u;
    }
}

// ---------------------------------------------------------------------------
// Kernel 2: fp16 mma.sync GEMM (fp32 accum) + fused ReLU/max/unorm16 epilogue.
// Measured-best config: 2 CTAs/SM, CTA 128x128, 256 threads, 8 warps
// (2 M x 4 N), warp tile 64x32. K chunks of 64, cp.async 3-stage pipeline,
// one __syncthreads per chunk. SMEM: 3 x 36864 B/CTA.
// (Legacy-HMMA roofline: ~13.6 cyc/MMA/SMSP — invariant to warps/CTAs/
// traffic/order/accumulator type/pipeline depth; this is the hardware rate.)
// ---------------------------------------------------------------------------
#define ROWB     144
#define T_A      0
#define T_B      18432
#define STAGE_SZ 36864
#define NSTAGE   3
#define DYN_SMEM (NSTAGE * STAGE_SZ)

__global__ void __launch_bounds__(256, 2)
softhebb_mma_gemm(int M, int N, int K)
{
    extern __shared__ char sm[];
    const uint32_t sbase = smem_u32(sm);

    const int tid  = threadIdx.x;
    const int wid  = tid >> 5;
    const int lane = tid & 31;
    const int wm   = wid & 1;   // M warp (0..1): rows wm*64..+63
    const int wn   = wid >> 1;  // N warp (0..3): cols wn*32..+31

    const int row0 = blockIdx.y * 128;
    const int col0 = blockIdx.x * 128;

    float acc[4][4][4];   // [mf(m16)][nf(n8)][quad]
    #pragma unroll
    for (int i = 0; i < 4; ++i)
        #pragma unroll
        for (int j = 0; j < 4; ++j)
            #pragma unroll
            for (int q = 0; q < 4; ++q) acc[i][j][q] = 0.f;

    const int nchunks = K >> 6;  // 32

    const uint32_t a_lm = (uint32_t)((wm * 64 + (lane & 15)) * ROWB + (lane >> 4) * 16);
    const uint32_t b_lm = (uint32_t)((wn * 32 + (lane & 7) + ((lane >> 4) << 3)) * ROWB
                                     + (((lane >> 3) & 1) << 4));

    // Per-stage load, 256 threads: A 1024 x 16B chunks (4/thread),
    // B 1024 chunks (4/thread) -> 8 CP16 per thread.
    #define LOAD_STAGE(chunk, stg) do {                                          \
        const int kel = (chunk) << 6;                                            \
        const uint32_t sb_ = sbase + (stg) * STAGE_SZ;                           \
        _Pragma("unroll")                                                        \
        for (int t = 0; t < 4; ++t) {                                            \
            const int c_ = tid + (t << 8);                                       \
            const int rr = c_ >> 3, q = c_ & 7;                                  \
            const uint32_t so = (uint32_t)(rr * ROWB + q * 16);                  \
            const size_t ga = (size_t)(row0 + rr) * K + kel + q * 8;             \
            const size_t gb = (size_t)(col0 + rr) * K + kel + q * 8;             \
            CP16(sb_ + T_A + so, g_xh + ga);                                     \
            CP16(sb_ + T_B + so, g_wh + gb);                                     \
        }                                                                        \
    } while (0)

    LOAD_STAGE(0, 0);
    CP_COMMIT();
    LOAD_STAGE(1, 1);
    CP_COMMIT();

    int cbuf = 0, lbuf = 2;
    for (int c = 0; c < nchunks; ++c) {
        CP_WAIT1();
        __syncthreads();

        if (c + 2 < nchunks) LOAD_STAGE(c + 2, lbuf);
        CP_COMMIT();

        const uint32_t sb = sbase + cbuf * STAGE_SZ;
        #pragma unroll
        for (int kk = 0; kk < 4; ++kk) {
            const uint32_t ko = kk << 5;
            uint32_t ah[4][4];
            uint32_t bh[2][4];
            #pragma unroll
            for (int mf = 0; mf < 4; ++mf) {
                const uint32_t ao = a_lm + mf * (16 * ROWB) + ko;
                LDSM_X4(ah[mf][0], ah[mf][1], ah[mf][2], ah[mf][3], sb + T_A + ao);
            }
            #pragma unroll
            for (int np = 0; np < 2; ++np) {
                const uint32_t bo = b_lm + np * (16 * ROWB) + ko;
                LDSM_X4(bh[np][0], bh[np][1], bh[np][2], bh[np][3], sb + T_B + bo);
            }
            #pragma unroll
            for (int np = 0; np < 2; ++np) {
                #pragma unroll
                for (int mf = 0; mf < 4; ++mf) {
                    MMA_F16(acc[mf][2 * np],     ah[mf], (&bh[np][0]));
                    MMA_F16(acc[mf][2 * np + 1], ah[mf], (&bh[np][2]));
                }
            }
        }

        cbuf = (cbuf == NSTAGE - 1) ? 0 : cbuf + 1;
        lbuf = (lbuf == NSTAGE - 1) ? 0 : lbuf + 1;
    }

    // Epilogue: ReLU + clamp + unorm16 store + global max
    const int g  = lane >> 2;
    const int tg = lane & 3;
    float tmax = 0.f;
    #pragma unroll
    for (int mf = 0; mf < 4; ++mf) {
        const int ra = row0 + wm * 64 + mf * 16 + g;
        #pragma unroll
        for (int nf = 0; nf < 4; ++nf) {
            const int col = col0 + wn * 32 + nf * 8 + tg * 2;
            float a0 = fminf(fmaxf(acc[mf][nf][0], 0.f), 1.f);
            float a1 = fminf(fmaxf(acc[mf][nf][1], 0.f), 1.f);
            float b0 = fminf(fmaxf(acc[mf][nf][2], 0.f), 1.f);
            float b1 = fminf(fmaxf(acc[mf][nf][3], 0.f), 1.f);
            tmax = fmaxf(tmax, fmaxf(fmaxf(a0, a1), fmaxf(b0, b1)));
            const uint32_t p0 = __float2uint_rn(a0 * 65535.f) |
                                (__float2uint_rn(a1 * 65535.f) << 16);
            const uint32_t p1 = __float2uint_rn(b0 * 65535.f) |
                                (__float2uint_rn(b1 * 65535.f) << 16);
            *reinterpret_cast<uint32_t*>(&g_u[(size_t)ra * N + col])       = p0;
            *reinterpret_cast<uint32_t*>(&g_u[(size_t)(ra + 8) * N + col]) = p1;
        }
    }

    #pragma unroll
    for (int o = 16; o; o >>= 1)
        tmax = fmaxf(tmax, __shfl_xor_sync(0xffffffffu, tmax, o));
    __shared__ float wmax[8];
    if (lane == 0) wmax[wid] = tmax;
    __syncthreads();
    if (tid == 0) {
        float m = wmax[0];
        #pragma unroll
        for (int i = 1; i < 8; ++i) m = fmaxf(m, wmax[i]);
        atomicMax(reinterpret_cast<int*>(&g_gmax), __float_as_int(m));
    }
}

// ---------------------------------------------------------------------------
// Kernel 3: per-row power-law + logprior + row-sum normalize.
// unorm16 u via __ldg, y via st.global.cs (streaming: never re-read).
// Fast path for lamb == 4 (u^4 = (u^2)^2, no MUFU).
// ---------------------------------------------------------------------------
__global__ void __launch_bounds__(256)
finalize_kernel(const float* __restrict__ logprior, const float* __restrict__ lamb_p,
                float* __restrict__ y, int N)
{
    const int r = blockIdx.x;
    const float lamb = lamb_p[0];
    const bool l4 = (lamb == 4.0f);
    const float inv_umax = 1.f / (g_gmax + EPSV);
    const float dq = 1.f / 65535.f;

    const int i = threadIdx.x;   // 256 threads, 8 u values each (N=2048)
    const uint4 q = __ldg(&reinterpret_cast<const uint4*>(g_u + (size_t)r * N)[i]);
    const float4 lp0 = __ldg(&reinterpret_cast<const float4*>(logprior)[2 * i]);
    const float4 lp1 = __ldg(&reinterpret_cast<const float4*>(logprior)[2 * i + 1]);

    float u[8];
    u[0] = (float)(q.x & 0xffff) * dq; u[1] = (float)(q.x >> 16) * dq;
    u[2] = (float)(q.y & 0xffff) * dq; u[3] = (float)(q.y >> 16) * dq;
    u[4] = (float)(q.z & 0xffff) * dq; u[5] = (float)(q.z >> 16) * dq;
    u[6] = (float)(q.w & 0xffff) * dq; u[7] = (float)(q.w >> 16) * dq;
    const float lp[8] = {lp0.x, lp0.y, lp0.z, lp0.w, lp1.x, lp1.y, lp1.z, lp1.w};

    float p[8];
    float s = 0.f;
    #pragma unroll
    for (int j = 0; j < 8; ++j) {
        const float un = u[j] * inv_umax;
        float pw;
        if (l4) { const float u2 = un * un; pw = u2 * u2; }
        else    { pw = exp2f(lamb * log2f(un)); }
        p[j] = (u[j] > 0.f) ? pw * expf(lp[j]) : 0.f;
        s += p[j];
    }

    #pragma unroll
    for (int o = 16; o; o >>= 1) s += __shfl_xor_sync(0xffffffffu, s, o);
    __shared__ float red[8];
    __shared__ float inv_sum_sh;
    const int lane = threadIdx.x & 31, wid = threadIdx.x >> 5;
    if (lane == 0) red[wid] = s;
    __syncthreads();
    if (threadIdx.x == 0) {
        float t = 0.f;
        for (int k = 0; k < 8; ++k) t += red[k];
        inv_sum_sh = 1.f / (t + EPSV);
    }
    __syncthreads();
    const float inv_sum = inv_sum_sh;

    float* yrow = y + (size_t)r * N;
    float4 o0, o1;
    o0.x = p[0] * inv_sum; o0.y = p[1] * inv_sum;
    o0.z = p[2] * inv_sum; o0.w = p[3] * inv_sum;
    o1.x = p[4] * inv_sum; o1.y = p[5] * inv_sum;
    o1.z = p[6] * inv_sum; o1.w = p[7] * inv_sum;
    STG_CS_V4(yrow + 8 * i,     o0);
    STG_CS_V4(yrow + 8 * i + 4, o1);
}

// ---------------------------------------------------------------------------
// Launcher. Inputs: x [B,IN] f32, weight [OUT,IN] f32, logprior [OUT] f32,
// lamb [1] f32. Output: y [B,OUT] f32.
// ---------------------------------------------------------------------------
extern "C" void kernel_launch(void* const* d_in, const int* in_sizes, int n_in,
                              void* d_out, int out_size)
{
    const float* x        = (const float*)d_in[0];
    const float* w        = (const float*)d_in[1];
    const float* logprior = (const float*)d_in[2];
    const float* lamb     = (const float*)d_in[3];
    float* y              = (float*)d_out;

    const int OUT = in_sizes[2];
    const int IN  = in_sizes[1] / OUT;
    const int B   = in_sizes[0] / IN;

    cudaFuncSetAttribute(softhebb_mma_gemm,
                         cudaFuncAttributeMaxDynamicSharedMemorySize, DYN_SMEM);

    prep_kernel<<<(B + OUT + 7) / 8, 256>>>(x, w, B, OUT, IN);

    dim3 grid(OUT / 128, B / 128);
    softhebb_mma_gemm<<<grid, 256, DYN_SMEM>>>(B, OUT, IN);

    finalize_kernel<<<B, 256>>>(logprior, lamb, y, OUT);
}

// round 16
// speedup vs baseline: 1.0017x; 1.0017x over previous
#include <cuda_runtime.h>
#include <cuda_fp16.h>
#include <cstdint>

#define EPSV 1e-9f

// Fixed problem shape: B=16384, IN=K=2048, OUT=2048
#define B_DIM   16384
#define K_DIM   2048
#define O_DIM   2048

// ---------------------------------------------------------------------------
// Device scratch (no allocations allowed in kernel_launch)
// ---------------------------------------------------------------------------
__device__ uint16_t g_u[(size_t)B_DIM * O_DIM];   // relu(cos) scratch, unorm16 (64 MB)
__device__ float g_gmax;
__device__ __align__(16) __half g_xh[(size_t)B_DIM * K_DIM];  // normalized x, fp16
__device__ __align__(16) __half g_wh[(size_t)O_DIM * K_DIM];  // normalized w, fp16

// ---------------------------------------------------------------------------
// PTX helpers (family-safe: ldmatrix, mma.sync, cp.async)
// ---------------------------------------------------------------------------
__device__ __forceinline__ uint32_t smem_u32(const void* p) {
    uint32_t a;
    asm("{ .reg .u64 t; cvta.to.shared.u64 t, %1; cvt.u32.u64 %0, t; }"
        : "=r"(a) : "l"(p));
    return a;
}

#define CP16(saddr, gptr) \
    asm volatile("cp.async.cg.shared.global [%0], [%1], 16;" \
                 :: "r"(saddr), "l"(gptr) : "memory")
#define CP_COMMIT() asm volatile("cp.async.commit_group;" ::: "memory")
#define CP_WAIT1()  asm volatile("cp.async.wait_group 1;" ::: "memory")

#define LDSM_X4(r0, r1, r2, r3, addr) \
    asm volatile("ldmatrix.sync.aligned.m8n8.x4.shared.b16 {%0,%1,%2,%3}, [%4];" \
                 : "=r"(r0), "=r"(r1), "=r"(r2), "=r"(r3) : "r"(addr))

#define MMA_F16(d, a, b) \
    asm volatile("mma.sync.aligned.m16n8k16.row.col.f32.f16.f16.f32 " \
                 "{%0,%1,%2,%3}, {%4,%5,%6,%7}, {%8,%9}, {%0,%1,%2,%3};" \
                 : "+f"((d)[0]), "+f"((d)[1]), "+f"((d)[2]), "+f"((d)[3]) \
                 : "r"((a)[0]), "r"((a)[1]), "r"((a)[2]), "r"((a)[3]),   \
                   "r"((b)[0]), "r"((b)[1]))

// ---------------------------------------------------------------------------
// Kernel 1: per-row L2 normalize -> fp16. Warp-per-row, reg-resident,
// shfl-only reduction, no smem/barriers. 8 rows per 256-thread block.
// Rows [0,B): x -> g_xh; [B,B+OUT): w -> g_wh. Block 0 resets g_gmax.
// (Measured: ~30us at 79% DRAM — at the memory floor.)
// ---------------------------------------------------------------------------
__global__ void __launch_bounds__(256)
prep_kernel(const float* __restrict__ x, const float* __restrict__ w,
            int B, int OUT, int IN)
{
    const int warp = threadIdx.x >> 5;
    const int lane = threadIdx.x & 31;
    const int r = blockIdx.x * 8 + warp;

    if (blockIdx.x == 0 && threadIdx.x == 0) g_gmax = 0.f;
    if (r >= B + OUT) return;

    const float* src;
    __half* dst;
    if (r < B) { src = x + (size_t)r * IN;       dst = g_xh + (size_t)r * IN; }
    else       { src = w + (size_t)(r - B) * IN; dst = g_wh + (size_t)(r - B) * IN; }

    const float4* p4 = reinterpret_cast<const float4*>(src);
    float4 v[16];
    #pragma unroll
    for (int j = 0; j < 16; ++j) v[j] = p4[lane + j * 32];

    float s = 0.f;
    #pragma unroll
    for (int j = 0; j < 16; ++j)
        s += v[j].x * v[j].x + v[j].y * v[j].y + v[j].z * v[j].z + v[j].w * v[j].w;

    #pragma unroll
    for (int o = 16; o; o >>= 1) s += __shfl_xor_sync(0xffffffffu, s, o);
    const float sc = 1.f / (sqrtf(s) + EPSV);

    uint2* d2 = reinterpret_cast<uint2*>(dst);
    #pragma unroll
    for (int j = 0; j < 16; ++j) {
        __half2 lo = __floats2half2_rn(v[j].x * sc, v[j].y * sc);
        __half2 hi = __floats2half2_rn(v[j].z * sc, v[j].w * sc);
        uint2 u;
        u.x = *reinterpret_cast<uint32_t*>(&lo);
        u.y = *reinterpret_cast<uint32_t*>(&hi);
        d2[lane + j * 32] = u;
    }
}

// ---------------------------------------------------------------------------
// Kernel 2: fp16 mma.sync GEMM (fp32 accum) + fused ReLU/max/unorm16 epilogue.
// Measured-best config: 2 CTAs/SM, CTA 128x128, 256 threads, 8 warps
// (2 M x 4 N), warp tile 64x32. K chunks of 64, cp.async 3-stage pipeline,
// one __syncthreads per chunk. SMEM: 3 x 36864 B/CTA.
// (Legacy-HMMA roofline: ~13.6 cyc/MMA/SMSP — invariant to warps/CTAs/
// traffic/order/accumulator type/pipeline depth/cache hints; this is the
// hardware rate of the only tensor path the family sm_103 target compiles.)
// ---------------------------------------------------------------------------
#define ROWB     144
#define T_A      0
#define T_B      18432
#define STAGE_SZ 36864
#define NSTAGE   3
#define DYN_SMEM (NSTAGE * STAGE_SZ)

__global__ void __launch_bounds__(256, 2)
softhebb_mma_gemm(int M, int N, int K)
{
    extern __shared__ char sm[];
    const uint32_t sbase = smem_u32(sm);

    const int tid  = threadIdx.x;
    const int wid  = tid >> 5;
    const int lane = tid & 31;
    const int wm   = wid & 1;   // M warp (0..1): rows wm*64..+63
    const int wn   = wid >> 1;  // N warp (0..3): cols wn*32..+31

    const int row0 = blockIdx.y * 128;
    const int col0 = blockIdx.x * 128;

    float acc[4][4][4];   // [mf(m16)][nf(n8)][quad]
    #pragma unroll
    for (int i = 0; i < 4; ++i)
        #pragma unroll
        for (int j = 0; j < 4; ++j)
            #pragma unroll
            for (int q = 0; q < 4; ++q) acc[i][j][q] = 0.f;

    const int nchunks = K >> 6;  // 32

    const uint32_t a_lm = (uint32_t)((wm * 64 + (lane & 15)) * ROWB + (lane >> 4) * 16);
    const uint32_t b_lm = (uint32_t)((wn * 32 + (lane & 7) + ((lane >> 4) << 3)) * ROWB
                                     + (((lane >> 3) & 1) << 4));

    // Per-stage load, 256 threads: A 1024 x 16B chunks (4/thread),
    // B 1024 chunks (4/thread) -> 8 CP16 per thread.
    #define LOAD_STAGE(chunk, stg) do {                                          \
        const int kel = (chunk) << 6;                                            \
        const uint32_t sb_ = sbase + (stg) * STAGE_SZ;                           \
        _Pragma("unroll")                                                        \
        for (int t = 0; t < 4; ++t) {                                            \
            const int c_ = tid + (t << 8);                                       \
            const int rr = c_ >> 3, q = c_ & 7;                                  \
            const uint32_t so = (uint32_t)(rr * ROWB + q * 16);                  \
            const size_t ga = (size_t)(row0 + rr) * K + kel + q * 8;             \
            const size_t gb = (size_t)(col0 + rr) * K + kel + q * 8;             \
            CP16(sb_ + T_A + so, g_xh + ga);                                     \
            CP16(sb_ + T_B + so, g_wh + gb);                                     \
        }                                                                        \
    } while (0)

    LOAD_STAGE(0, 0);
    CP_COMMIT();
    LOAD_STAGE(1, 1);
    CP_COMMIT();

    int cbuf = 0, lbuf = 2;
    for (int c = 0; c < nchunks; ++c) {
        CP_WAIT1();
        __syncthreads();

        if (c + 2 < nchunks) LOAD_STAGE(c + 2, lbuf);
        CP_COMMIT();

        const uint32_t sb = sbase + cbuf * STAGE_SZ;
        #pragma unroll
        for (int kk = 0; kk < 4; ++kk) {
            const uint32_t ko = kk << 5;
            uint32_t ah[4][4];
            uint32_t bh[2][4];
            #pragma unroll
            for (int mf = 0; mf < 4; ++mf) {
                const uint32_t ao = a_lm + mf * (16 * ROWB) + ko;
                LDSM_X4(ah[mf][0], ah[mf][1], ah[mf][2], ah[mf][3], sb + T_A + ao);
            }
            #pragma unroll
            for (int np = 0; np < 2; ++np) {
                const uint32_t bo = b_lm + np * (16 * ROWB) + ko;
                LDSM_X4(bh[np][0], bh[np][1], bh[np][2], bh[np][3], sb + T_B + bo);
            }
            #pragma unroll
            for (int np = 0; np < 2; ++np) {
                #pragma unroll
                for (int mf = 0; mf < 4; ++mf) {
                    MMA_F16(acc[mf][2 * np],     ah[mf], (&bh[np][0]));
                    MMA_F16(acc[mf][2 * np + 1], ah[mf], (&bh[np][2]));
                }
            }
        }

        cbuf = (cbuf == NSTAGE - 1) ? 0 : cbuf + 1;
        lbuf = (lbuf == NSTAGE - 1) ? 0 : lbuf + 1;
    }

    // Epilogue: ReLU + clamp + unorm16 store + global max
    const int g  = lane >> 2;
    const int tg = lane & 3;
    float tmax = 0.f;
    #pragma unroll
    for (int mf = 0; mf < 4; ++mf) {
        const int ra = row0 + wm * 64 + mf * 16 + g;
        #pragma unroll
        for (int nf = 0; nf < 4; ++nf) {
            const int col = col0 + wn * 32 + nf * 8 + tg * 2;
            float a0 = fminf(fmaxf(acc[mf][nf][0], 0.f), 1.f);
            float a1 = fminf(fmaxf(acc[mf][nf][1], 0.f), 1.f);
            float b0 = fminf(fmaxf(acc[mf][nf][2], 0.f), 1.f);
            float b1 = fminf(fmaxf(acc[mf][nf][3], 0.f), 1.f);
            tmax = fmaxf(tmax, fmaxf(fmaxf(a0, a1), fmaxf(b0, b1)));
            const uint32_t p0 = __float2uint_rn(a0 * 65535.f) |
                                (__float2uint_rn(a1 * 65535.f) << 16);
            const uint32_t p1 = __float2uint_rn(b0 * 65535.f) |
                                (__float2uint_rn(b1 * 65535.f) << 16);
            *reinterpret_cast<uint32_t*>(&g_u[(size_t)ra * N + col])       = p0;
            *reinterpret_cast<uint32_t*>(&g_u[(size_t)(ra + 8) * N + col]) = p1;
        }
    }

    #pragma unroll
    for (int o = 16; o; o >>= 1)
        tmax = fmaxf(tmax, __shfl_xor_sync(0xffffffffu, tmax, o));
    __shared__ float wmax[8];
    if (lane == 0) wmax[wid] = tmax;
    __syncthreads();
    if (tid == 0) {
        float m = wmax[0];
        #pragma unroll
        for (int i = 1; i < 8; ++i) m = fmaxf(m, wmax[i]);
        atomicMax(reinterpret_cast<int*>(&g_gmax), __float_as_int(m));
    }
}

// ---------------------------------------------------------------------------
// Kernel 3: per-row power-law + logprior + row-sum normalize.
// unorm16 u, reg-resident. Fast path for lamb == 4 (u^4 = (u^2)^2, no MUFU).
// (Measured: ~24us — at the memory floor.)
// ---------------------------------------------------------------------------
__global__ void __launch_bounds__(256)
finalize_kernel(const float* __restrict__ logprior, const float* __restrict__ lamb_p,
                float* __restrict__ y, int N)
{
    const int r = blockIdx.x;
    const float lamb = lamb_p[0];
    const bool l4 = (lamb == 4.0f);
    const float inv_umax = 1.f / (g_gmax + EPSV);
    const float dq = 1.f / 65535.f;

    const int i = threadIdx.x;   // 256 threads, 8 u values each (N=2048)
    const uint4 q = reinterpret_cast<const uint4*>(g_u + (size_t)r * N)[i];
    const float4 lp0 = reinterpret_cast<const float4*>(logprior)[2 * i];
    const float4 lp1 = reinterpret_cast<const float4*>(logprior)[2 * i + 1];

    float u[8];
    u[0] = (float)(q.x & 0xffff) * dq; u[1] = (float)(q.x >> 16) * dq;
    u[2] = (float)(q.y & 0xffff) * dq; u[3] = (float)(q.y >> 16) * dq;
    u[4] = (float)(q.z & 0xffff) * dq; u[5] = (float)(q.z >> 16) * dq;
    u[6] = (float)(q.w & 0xffff) * dq; u[7] = (float)(q.w >> 16) * dq;
    const float lp[8] = {lp0.x, lp0.y, lp0.z, lp0.w, lp1.x, lp1.y, lp1.z, lp1.w};

    float p[8];
    float s = 0.f;
    #pragma unroll
    for (int j = 0; j < 8; ++j) {
        const float un = u[j] * inv_umax;
        float pw;
        if (l4) { const float u2 = un * un; pw = u2 * u2; }
        else    { pw = exp2f(lamb * log2f(un)); }
        p[j] = (u[j] > 0.f) ? pw * expf(lp[j]) : 0.f;
        s += p[j];
    }

    #pragma unroll
    for (int o = 16; o; o >>= 1) s += __shfl_xor_sync(0xffffffffu, s, o);
    __shared__ float red[8];
    __shared__ float inv_sum_sh;
    const int lane = threadIdx.x & 31, wid = threadIdx.x >> 5;
    if (lane == 0) red[wid] = s;
    __syncthreads();
    if (threadIdx.x == 0) {
        float t = 0.f;
        for (int k = 0; k < 8; ++k) t += red[k];
        inv_sum_sh = 1.f / (t + EPSV);
    }
    __syncthreads();
    const float inv_sum = inv_sum_sh;

    float4* y4 = reinterpret_cast<float4*>(y + (size_t)r * N);
    float4 o0, o1;
    o0.x = p[0] * inv_sum; o0.y = p[1] * inv_sum;
    o0.z = p[2] * inv_sum; o0.w = p[3] * inv_sum;
    o1.x = p[4] * inv_sum; o1.y = p[5] * inv_sum;
    o1.z = p[6] * inv_sum; o1.w = p[7] * inv_sum;
    y4[2 * i]     = o0;
    y4[2 * i + 1] = o1;
}

// ---------------------------------------------------------------------------
// Launcher. Inputs: x [B,IN] f32, weight [OUT,IN] f32, logprior [OUT] f32,
// lamb [1] f32. Output: y [B,OUT] f32.
// ---------------------------------------------------------------------------
extern "C" void kernel_launch(void* const* d_in, const int* in_sizes, int n_in,
                              void* d_out, int out_size)
{
    const float* x        = (const float*)d_in[0];
    const float* w        = (const float*)d_in[1];
    const float* logprior = (const float*)d_in[2];
    const float* lamb     = (const float*)d_in[3];
    float* y              = (float*)d_out;

    const int OUT = in_sizes[2];
    const int IN  = in_sizes[1] / OUT;
    const int B   = in_sizes[0] / IN;

    cudaFuncSetAttribute(softhebb_mma_gemm,
                         cudaFuncAttributeMaxDynamicSharedMemorySize, DYN_SMEM);

    prep_kernel<<<(B + OUT + 7) / 8, 256>>>(x, w, B, OUT, IN);

    dim3 grid(OUT / 128, B / 128);
    softhebb_mma_gemm<<<grid, 256, DYN_SMEM>>>(B, OUT, IN);

    finalize_kernel<<<B, 256>>>(logprior, lamb, y, OUT);
}

// round 17
// speedup vs baseline: 1.0045x; 1.0028x over previous
#include <cuda_runtime.h>
#include <cuda_fp16.h>
#include <cstdint>

#define EPSV 1e-9f

// Fixed problem shape: B=16384, IN=K=2048, OUT=2048
#define B_DIM   16384
#define K_DIM   2048
#define O_DIM   2048

// ---------------------------------------------------------------------------
// Device scratch (no allocations allowed in kernel_launch)
// ---------------------------------------------------------------------------
__device__ uint16_t g_u[(size_t)B_DIM * O_DIM];   // relu(cos) scratch, unorm16 (64 MB)
__device__ float g_gmax;
__device__ __align__(16) __half g_xh[(size_t)B_DIM * K_DIM];  // normalized x, fp16
__device__ __align__(16) __half g_wh[(size_t)O_DIM * K_DIM];  // normalized w, fp16

// ---------------------------------------------------------------------------
// PTX helpers (family-safe: ldmatrix, mma.sync, cp.async)
// ---------------------------------------------------------------------------
__device__ __forceinline__ uint32_t smem_u32(const void* p) {
    uint32_t a;
    asm("{ .reg .u64 t; cvta.to.shared.u64 t, %1; cvt.u32.u64 %0, t; }"
        : "=r"(a) : "l"(p));
    return a;
}

#define CP16(saddr, gptr) \
    asm volatile("cp.async.cg.shared.global [%0], [%1], 16;" \
                 :: "r"(saddr), "l"(gptr) : "memory")
#define CP_COMMIT() asm volatile("cp.async.commit_group;" ::: "memory")
#define CP_WAIT1()  asm volatile("cp.async.wait_group 1;" ::: "memory")

#define LDSM_X4(r0, r1, r2, r3, addr) \
    asm volatile("ldmatrix.sync.aligned.m8n8.x4.shared.b16 {%0,%1,%2,%3}, [%4];" \
                 : "=r"(r0), "=r"(r1), "=r"(r2), "=r"(r3) : "r"(addr))

#define MMA_F16(d, a, b) \
    asm volatile("mma.sync.aligned.m16n8k16.row.col.f32.f16.f16.f32 " \
                 "{%0,%1,%2,%3}, {%4,%5,%6,%7}, {%8,%9}, {%0,%1,%2,%3};" \
                 : "+f"((d)[0]), "+f"((d)[1]), "+f"((d)[2]), "+f"((d)[3]) \
                 : "r"((a)[0]), "r"((a)[1]), "r"((a)[2]), "r"((a)[3]),   \
                   "r"((b)[0]), "r"((b)[1]))

// ---------------------------------------------------------------------------
// Kernel 1: per-row L2 normalize -> fp16. Warp-per-row, reg-resident,
// shfl-only reduction, no smem/barriers. 8 rows per 256-thread block.
// Rows [0,B): x -> g_xh; [B,B+OUT): w -> g_wh. Block 0 resets g_gmax.
// (Measured: ~30us at 79% DRAM — at the memory floor.)
// ---------------------------------------------------------------------------
__global__ void __launch_bounds__(256)
prep_kernel(const float* __restrict__ x, const float* __restrict__ w,
            int B, int OUT, int IN)
{
    const int warp = threadIdx.x >> 5;
    const int lane = threadIdx.x & 31;
    const int r = blockIdx.x * 8 + warp;

    if (blockIdx.x == 0 && threadIdx.x == 0) g_gmax = 0.f;
    if (r >= B + OUT) return;

    const float* src;
    __half* dst;
    if (r < B) { src = x + (size_t)r * IN;       dst = g_xh + (size_t)r * IN; }
    else       { src = w + (size_t)(r - B) * IN; dst = g_wh + (size_t)(r - B) * IN; }

    const float4* p4 = reinterpret_cast<const float4*>(src);
    float4 v[16];
    #pragma unroll
    for (int j = 0; j < 16; ++j) v[j] = p4[lane + j * 32];

    float s = 0.f;
    #pragma unroll
    for (int j = 0; j < 16; ++j)
        s += v[j].x * v[j].x + v[j].y * v[j].y + v[j].z * v[j].z + v[j].w * v[j].w;

    #pragma unroll
    for (int o = 16; o; o >>= 1) s += __shfl_xor_sync(0xffffffffu, s, o);
    const float sc = 1.f / (sqrtf(s) + EPSV);

    uint2* d2 = reinterpret_cast<uint2*>(dst);
    #pragma unroll
    for (int j = 0; j < 16; ++j) {
        __half2 lo = __floats2half2_rn(v[j].x * sc, v[j].y * sc);
        __half2 hi = __floats2half2_rn(v[j].z * sc, v[j].w * sc);
        uint2 u;
        u.x = *reinterpret_cast<uint32_t*>(&lo);
        u.y = *reinterpret_cast<uint32_t*>(&hi);
        d2[lane + j * 32] = u;
    }
}

// ---------------------------------------------------------------------------
// Kernel 2: fp16 mma.sync GEMM (fp32 accum) + fused ReLU/max/unorm16 epilogue.
// Measured-best config: 2 CTAs/SM, CTA 128x128, 256 threads, 8 warps
// (2 M x 4 N), warp tile 64x32. K chunks of 64, cp.async 3-stage pipeline,
// one __syncthreads per chunk. SMEM: 3 x 36864 B/CTA.
// (Legacy-HMMA roofline: ~13.6 cyc/MMA/SMSP — invariant to warps/CTAs/
// traffic/order/accumulator type/pipeline depth/cache hints; this is the
// hardware rate of the only tensor path the family sm_103 target compiles.)
// ---------------------------------------------------------------------------
#define ROWB     144
#define T_A      0
#define T_B      18432
#define STAGE_SZ 36864
#define NSTAGE   3
#define DYN_SMEM (NSTAGE * STAGE_SZ)

__global__ void __launch_bounds__(256, 2)
softhebb_mma_gemm(int M, int N, int K)
{
    extern __shared__ char sm[];
    const uint32_t sbase = smem_u32(sm);

    const int tid  = threadIdx.x;
    const int wid  = tid >> 5;
    const int lane = tid & 31;
    const int wm   = wid & 1;   // M warp (0..1): rows wm*64..+63
    const int wn   = wid >> 1;  // N warp (0..3): cols wn*32..+31

    const int row0 = blockIdx.y * 128;
    const int col0 = blockIdx.x * 128;

    float acc[4][4][4];   // [mf(m16)][nf(n8)][quad]
    #pragma unroll
    for (int i = 0; i < 4; ++i)
        #pragma unroll
        for (int j = 0; j < 4; ++j)
            #pragma unroll
            for (int q = 0; q < 4; ++q) acc[i][j][q] = 0.f;

    const int nchunks = K >> 6;  // 32

    const uint32_t a_lm = (uint32_t)((wm * 64 + (lane & 15)) * ROWB + (lane >> 4) * 16);
    const uint32_t b_lm = (uint32_t)((wn * 32 + (lane & 7) + ((lane >> 4) << 3)) * ROWB
                                     + (((lane >> 3) & 1) << 4));

    // Per-stage load, 256 threads: A 1024 x 16B chunks (4/thread),
    // B 1024 chunks (4/thread) -> 8 CP16 per thread.
    #define LOAD_STAGE(chunk, stg) do {                                          \
        const int kel = (chunk) << 6;                                            \
        const uint32_t sb_ = sbase + (stg) * STAGE_SZ;                           \
        _Pragma("unroll")                                                        \
        for (int t = 0; t < 4; ++t) {                                            \
            const int c_ = tid + (t << 8);                                       \
            const int rr = c_ >> 3, q = c_ & 7;                                  \
            const uint32_t so = (uint32_t)(rr * ROWB + q * 16);                  \
            const size_t ga = (size_t)(row0 + rr) * K + kel + q * 8;             \
            const size_t gb = (size_t)(col0 + rr) * K + kel + q * 8;             \
            CP16(sb_ + T_A + so, g_xh + ga);                                     \
            CP16(sb_ + T_B + so, g_wh + gb);                                     \
        }                                                                        \
    } while (0)

    LOAD_STAGE(0, 0);
    CP_COMMIT();
    LOAD_STAGE(1, 1);
    CP_COMMIT();

    int cbuf = 0, lbuf = 2;
    for (int c = 0; c < nchunks; ++c) {
        CP_WAIT1();
        __syncthreads();

        if (c + 2 < nchunks) LOAD_STAGE(c + 2, lbuf);
        CP_COMMIT();

        const uint32_t sb = sbase + cbuf * STAGE_SZ;
        #pragma unroll
        for (int kk = 0; kk < 4; ++kk) {
            const uint32_t ko = kk << 5;
            uint32_t ah[4][4];
            uint32_t bh[2][4];
            #pragma unroll
            for (int mf = 0; mf < 4; ++mf) {
                const uint32_t ao = a_lm + mf * (16 * ROWB) + ko;
                LDSM_X4(ah[mf][0], ah[mf][1], ah[mf][2], ah[mf][3], sb + T_A + ao);
            }
            #pragma unroll
            for (int np = 0; np < 2; ++np) {
                const uint32_t bo = b_lm + np * (16 * ROWB) + ko;
                LDSM_X4(bh[np][0], bh[np][1], bh[np][2], bh[np][3], sb + T_B + bo);
            }
            #pragma unroll
            for (int np = 0; np < 2; ++np) {
                #pragma unroll
                for (int mf = 0; mf < 4; ++mf) {
                    MMA_F16(acc[mf][2 * np],     ah[mf], (&bh[np][0]));
                    MMA_F16(acc[mf][2 * np + 1], ah[mf], (&bh[np][2]));
                }
            }
        }

        cbuf = (cbuf == NSTAGE - 1) ? 0 : cbuf + 1;
        lbuf = (lbuf == NSTAGE - 1) ? 0 : lbuf + 1;
    }

    // Epilogue: ReLU + clamp + unorm16 store + global max
    const int g  = lane >> 2;
    const int tg = lane & 3;
    float tmax = 0.f;
    #pragma unroll
    for (int mf = 0; mf < 4; ++mf) {
        const int ra = row0 + wm * 64 + mf * 16 + g;
        #pragma unroll
        for (int nf = 0; nf < 4; ++nf) {
            const int col = col0 + wn * 32 + nf * 8 + tg * 2;
            float a0 = fminf(fmaxf(acc[mf][nf][0], 0.f), 1.f);
            float a1 = fminf(fmaxf(acc[mf][nf][1], 0.f), 1.f);
            float b0 = fminf(fmaxf(acc[mf][nf][2], 0.f), 1.f);
            float b1 = fminf(fmaxf(acc[mf][nf][3], 0.f), 1.f);
            tmax = fmaxf(tmax, fmaxf(fmaxf(a0, a1), fmaxf(b0, b1)));
            const uint32_t p0 = __float2uint_rn(a0 * 65535.f) |
                                (__float2uint_rn(a1 * 65535.f) << 16);
            const uint32_t p1 = __float2uint_rn(b0 * 65535.f) |
                                (__float2uint_rn(b1 * 65535.f) << 16);
            *reinterpret_cast<uint32_t*>(&g_u[(size_t)ra * N + col])       = p0;
            *reinterpret_cast<uint32_t*>(&g_u[(size_t)(ra + 8) * N + col]) = p1;
        }
    }

    #pragma unroll
    for (int o = 16; o; o >>= 1)
        tmax = fmaxf(tmax, __shfl_xor_sync(0xffffffffu, tmax, o));
    __shared__ float wmax[8];
    if (lane == 0) wmax[wid] = tmax;
    __syncthreads();
    if (tid == 0) {
        float m = wmax[0];
        #pragma unroll
        for (int i = 1; i < 8; ++i) m = fmaxf(m, wmax[i]);
        atomicMax(reinterpret_cast<int*>(&g_gmax), __float_as_int(m));
    }
}

// ---------------------------------------------------------------------------
// Kernel 3: per-row power-law + logprior + row-sum normalize.
// unorm16 u, reg-resident. Fast path for lamb == 4 (u^4 = (u^2)^2, no MUFU).
// (Measured: ~24us — at the memory floor.)
// ---------------------------------------------------------------------------
__global__ void __launch_bounds__(256)
finalize_kernel(const float* __restrict__ logprior, const float* __restrict__ lamb_p,
                float* __restrict__ y, int N)
{
    const int r = blockIdx.x;
    const float lamb = lamb_p[0];
    const bool l4 = (lamb == 4.0f);
    const float inv_umax = 1.f / (g_gmax + EPSV);
    const float dq = 1.f / 65535.f;

    const int i = threadIdx.x;   // 256 threads, 8 u values each (N=2048)
    const uint4 q = reinterpret_cast<const uint4*>(g_u + (size_t)r * N)[i];
    const float4 lp0 = reinterpret_cast<const float4*>(logprior)[2 * i];
    const float4 lp1 = reinterpret_cast<const float4*>(logprior)[2 * i + 1];

    float u[8];
    u[0] = (float)(q.x & 0xffff) * dq; u[1] = (float)(q.x >> 16) * dq;
    u[2] = (float)(q.y & 0xffff) * dq; u[3] = (float)(q.y >> 16) * dq;
    u[4] = (float)(q.z & 0xffff) * dq; u[5] = (float)(q.z >> 16) * dq;
    u[6] = (float)(q.w & 0xffff) * dq; u[7] = (float)(q.w >> 16) * dq;
    const float lp[8] = {lp0.x, lp0.y, lp0.z, lp0.w, lp1.x, lp1.y, lp1.z, lp1.w};

    float p[8];
    float s = 0.f;
    #pragma unroll
    for (int j = 0; j < 8; ++j) {
        const float un = u[j] * inv_umax;
        float pw;
        if (l4) { const float u2 = un * un; pw = u2 * u2; }
        else    { pw = exp2f(lamb * log2f(un)); }
        p[j] = (u[j] > 0.f) ? pw * expf(lp[j]) : 0.f;
        s += p[j];
    }

    #pragma unroll
    for (int o = 16; o; o >>= 1) s += __shfl_xor_sync(0xffffffffu, s, o);
    __shared__ float red[8];
    __shared__ float inv_sum_sh;
    const int lane = threadIdx.x & 31, wid = threadIdx.x >> 5;
    if (lane == 0) red[wid] = s;
    __syncthreads();
    if (threadIdx.x == 0) {
        float t = 0.f;
        for (int k = 0; k < 8; ++k) t += red[k];
        inv_sum_sh = 1.f / (t + EPSV);
    }
    __syncthreads();
    const float inv_sum = inv_sum_sh;

    float4* y4 = reinterpret_cast<float4*>(y + (size_t)r * N);
    float4 o0, o1;
    o0.x = p[0] * inv_sum; o0.y = p[1] * inv_sum;
    o0.z = p[2] * inv_sum; o0.w = p[3] * inv_sum;
    o1.x = p[4] * inv_sum; o1.y = p[5] * inv_sum;
    o1.z = p[6] * inv_sum; o1.w = p[7] * inv_sum;
    y4[2 * i]     = o0;
    y4[2 * i + 1] = o1;
}

// ---------------------------------------------------------------------------
// Launcher. Inputs: x [B,IN] f32, weight [OUT,IN] f32, logprior [OUT] f32,
// lamb [1] f32. Output: y [B,OUT] f32.
// ---------------------------------------------------------------------------
extern "C" void kernel_launch(void* const* d_in, const int* in_sizes, int n_in,
                              void* d_out, int out_size)
{
    const float* x        = (const float*)d_in[0];
    const float* w        = (const float*)d_in[1];
    const float* logprior = (const float*)d_in[2];
    const float* lamb     = (const float*)d_in[3];
    float* y              = (float*)d_out;

    const int OUT = in_sizes[2];
    const int IN  = in_sizes[1] / OUT;
    const int B   = in_sizes[0] / IN;

    cudaFuncSetAttribute(softhebb_mma_gemm,
                         cudaFuncAttributeMaxDynamicSharedMemorySize, DYN_SMEM);

    prep_kernel<<<(B + OUT + 7) / 8, 256>>>(x, w, B, OUT, IN);

    dim3 grid(OUT / 128, B / 128);
    softhebb_mma_gemm<<<grid, 256, DYN_SMEM>>>(B, OUT, IN);

    finalize_kernel<<<B, 256>>>(logprior, lamb, y, OUT);
}